// round 4
// baseline (speedup 1.0000x reference)
#include <cuda_runtime.h>

#define NN 100000
#define NE 1200000
#define NF 64
#define NH 256
#define NC 40
#define NITER 8

// ---------------- scratch (device globals; no allocation) ----------------
__device__ int   g_is64;            // 1 if edge_index is int64, 0 if int32
__device__ int   g_cnt[NN];
__device__ float g_dinv[NN];
__device__ int   g_rowptr[NN + 1];
__device__ int   g_cursor[NN];
__device__ int   g_bsum[256];
__device__ int   g_boff[256];
__device__ int   g_csr_col[NE];
__device__ float g_csr_w[NE];
__device__ __align__(16) float g_h0[NN * NF];
__device__ __align__(16) float g_h1[NN * NF];
__device__ __align__(16) float g_y[NN * NF];
__device__ __align__(16) float g_hid[NN * NH];

// ---------------- edge dtype detection ----------------
// If the buffer really holds int64 node ids, every value is in [0, NN).
// If it holds int32 pairs read as int64, values are >= 2^32 unless the high
// word happens to be 0 (prob ~1e-5 per sample; 1024 samples => impossible).
__global__ void k_detect(const void* ei) {
    __shared__ int bad;
    if (threadIdx.x == 0) bad = 0;
    __syncthreads();
    const long long* e64 = (const long long*)ei;
    for (int i = threadIdx.x; i < 1024; i += 256) {
        long long v = e64[i];
        if (v < 0 || v >= NN) bad = 1;
    }
    __syncthreads();
    if (threadIdx.x == 0) g_is64 = bad ? 0 : 1;
}

__device__ __forceinline__ int edge_at(const void* ei, int half, int e) {
    if (g_is64) return (int)((const long long*)ei)[half * NE + e];
    return ((const int*)ei)[half * NE + e];
}

// ---------------- preprocessing ----------------
__global__ void k_zero() {
    int i = blockIdx.x * blockDim.x + threadIdx.x;
    if (i < NN) g_cnt[i] = 0;
}

__global__ void k_hist(const void* __restrict__ ei) {
    int e = blockIdx.x * blockDim.x + threadIdx.x;
    if (e < NE) atomicAdd(&g_cnt[edge_at(ei, 0, e)], 1);
}

__global__ void k_dinv() {
    int i = blockIdx.x * blockDim.x + threadIdx.x;
    if (i < NN) g_dinv[i] = rsqrtf((float)(g_cnt[i] + 1));
}

// block-level exclusive scan (512 elems/block)
__global__ void k_scan1() {
    __shared__ int s[512];
    int t = threadIdx.x;
    int i = blockIdx.x * 512 + t;
    int v = (i < NN) ? g_cnt[i] : 0;
    s[t] = v;
    __syncthreads();
    for (int off = 1; off < 512; off <<= 1) {
        int add = (t >= off) ? s[t - off] : 0;
        __syncthreads();
        s[t] += add;
        __syncthreads();
    }
    if (i < NN) g_rowptr[i] = s[t] - v;      // exclusive within block
    if (t == 511) g_bsum[blockIdx.x] = s[511];
}

__global__ void k_scan2(int nb) {
    __shared__ int s[256];
    int t = threadIdx.x;
    int v = (t < nb) ? g_bsum[t] : 0;
    s[t] = v;
    __syncthreads();
    for (int off = 1; off < 256; off <<= 1) {
        int add = (t >= off) ? s[t - off] : 0;
        __syncthreads();
        s[t] += add;
        __syncthreads();
    }
    if (t < nb) g_boff[t] = s[t] - v;        // exclusive block offsets
}

__global__ void k_scan3() {
    int i = blockIdx.x * blockDim.x + threadIdx.x;
    if (i < NN) {
        int rp = g_rowptr[i] + g_boff[i >> 9];
        g_rowptr[i] = rp;
        g_cursor[i] = rp;
    }
    if (i == 0) g_rowptr[NN] = NE;
}

__global__ void k_scatter(const void* __restrict__ ei) {
    int e = blockIdx.x * blockDim.x + threadIdx.x;
    if (e < NE) {
        int r = edge_at(ei, 0, e);
        int c = edge_at(ei, 1, e);
        int pos = atomicAdd(&g_cursor[r], 1);
        g_csr_col[pos] = c;
        g_csr_w[pos]   = g_dinv[r] * g_dinv[c];
    }
}

// h0 = 0.5*x ; y = h0
__global__ void k_init(const float* __restrict__ x) {
    int i = blockIdx.x * blockDim.x + threadIdx.x;
    if (i < NN * (NF / 4)) {
        float4 v = ((const float4*)x)[i];
        v.x *= 0.5f; v.y *= 0.5f; v.z *= 0.5f; v.w *= 0.5f;
        ((float4*)g_h0)[i] = v;
        ((float4*)g_y)[i]  = v;
    }
}

// ---------------- SPMM: one warp per row, lane = 2 features ----------------
// h_out[r] = dinv[r]^2 * h_in[r] + sum_e w[e] * h_in[col[e]] ; y[r] += h_out[r]
__global__ void __launch_bounds__(256) k_spmm(int parity) {
    const float2* __restrict__ hin = (const float2*)(parity ? g_h1 : g_h0);
    float2* __restrict__ hout      = (float2*)(parity ? g_h0 : g_h1);

    __shared__ int   scol[8][32];
    __shared__ float swt[8][32];

    int lane = threadIdx.x & 31;
    int wid  = threadIdx.x >> 5;
    int r    = blockIdx.x * 8 + wid;   // NN divisible by 8

    int start = g_rowptr[r];
    int end   = g_rowptr[r + 1];
    float dr  = g_dinv[r];

    float2 hv = __ldg(&hin[r * 32 + lane]);
    float dw  = dr * dr;
    float2 acc;
    acc.x = dw * hv.x;
    acc.y = dw * hv.y;

    for (int b = start; b < end; b += 32) {
        int idx = b + lane;
        int c = 0; float w = 0.f;
        if (idx < end) { c = g_csr_col[idx]; w = g_csr_w[idx]; }
        scol[wid][lane] = c;
        swt[wid][lane]  = w;
        __syncwarp();
        int m = min(32, end - b);
#pragma unroll 4
        for (int j = 0; j < m; j++) {
            int   cj = scol[wid][j];
            float wj = swt[wid][j];
            float2 t = __ldg(&hin[cj * 32 + lane]);
            acc.x += wj * t.x;
            acc.y += wj * t.y;
        }
        __syncwarp();
    }

    hout[r * 32 + lane] = acc;
    float2* y2 = (float2*)g_y;
    float2 yv  = y2[r * 32 + lane];
    yv.x += acc.x;
    yv.y += acc.y;
    y2[r * 32 + lane] = yv;
}

// ---------------- GEMM1: hid = relu((y/9) @ W1 + b1) ----------------
// tile: 32 rows x 128 cols, 256 threads, 4x4 register tile per thread
__global__ void __launch_bounds__(256) k_gemm1(const float* __restrict__ W1,
                                               const float* __restrict__ b1) {
    __shared__ __align__(16) float As[32 * NF];     // 8 KB
    __shared__ __align__(16) float Bs[NF * 128];    // 32 KB

    int tid = threadIdx.x;
    int rb  = blockIdx.x * 32;
    int bn  = blockIdx.y * 128;

    const float4* y4 = (const float4*)g_y;
    float4* As4 = (float4*)As;
    for (int l = tid; l < 32 * 16; l += 256) {
        int rr = l >> 4, k4 = l & 15;
        As4[rr * 16 + k4] = y4[(rb + rr) * 16 + k4];
    }
    float4* Bs4 = (float4*)Bs;
    for (int l = tid; l < NF * 32; l += 256) {
        int kk = l >> 5, c4 = l & 31;
        Bs4[kk * 32 + c4] = *(const float4*)&W1[kk * NH + bn + c4 * 4];
    }
    __syncthreads();

    int tx = tid & 31, ty = tid >> 5;
    float acc[4][4] = {};
#pragma unroll
    for (int k = 0; k < NF; k++) {
        float4 bv = Bs4[k * 32 + tx];
#pragma unroll
        for (int i = 0; i < 4; i++) {
            float a = As[(ty * 4 + i) * NF + k];
            acc[i][0] += a * bv.x;
            acc[i][1] += a * bv.y;
            acc[i][2] += a * bv.z;
            acc[i][3] += a * bv.w;
        }
    }

    int c = bn + tx * 4;
    float4 bb = *(const float4*)&b1[c];
    const float inv9 = 1.0f / 9.0f;
#pragma unroll
    for (int i = 0; i < 4; i++) {
        int gr = rb + ty * 4 + i;
        float4 o;
        o.x = fmaxf(acc[i][0] * inv9 + bb.x, 0.f);
        o.y = fmaxf(acc[i][1] * inv9 + bb.y, 0.f);
        o.z = fmaxf(acc[i][2] * inv9 + bb.z, 0.f);
        o.w = fmaxf(acc[i][3] * inv9 + bb.w, 0.f);
        *(float4*)&g_hid[gr * NH + c] = o;
    }
}

// ---------------- GEMM2: out = hid @ W2 + b2 ----------------
// 256 rows/block, one row per thread, acc[40]; K chunked by 32
__global__ void __launch_bounds__(256) k_gemm2(const float* __restrict__ W2,
                                               const float* __restrict__ b2,
                                               float* __restrict__ out) {
    __shared__ float Ash[256 * 33];                 // ~33.8 KB, scalar access
    __shared__ __align__(16) float Bsh[32 * NC];    // 5 KB (float4 reads)

    int tid   = threadIdx.x;
    int rbase = blockIdx.x * 256;
    int row   = rbase + tid;

    float acc[NC];
#pragma unroll
    for (int j = 0; j < NC; j++) acc[j] = 0.f;

    for (int kc = 0; kc < NH; kc += 32) {
#pragma unroll
        for (int l = 0; l < 32; l++) {
            int li = l * 256 + tid;
            int rr = li >> 5, kk = li & 31;
            int gr = rbase + rr;
            Ash[rr * 33 + kk] = (gr < NN) ? g_hid[gr * NH + kc + kk] : 0.f;
        }
        for (int li = tid; li < 32 * NC; li += 256) {
            int kk = li / NC, c = li % NC;
            Bsh[kk * NC + c] = W2[(kc + kk) * NC + c];
        }
        __syncthreads();
#pragma unroll
        for (int kk = 0; kk < 32; kk++) {
            float a = Ash[tid * 33 + kk];
#pragma unroll
            for (int j4 = 0; j4 < NC / 4; j4++) {
                float4 b = *(const float4*)&Bsh[kk * NC + j4 * 4];
                acc[j4 * 4 + 0] += a * b.x;
                acc[j4 * 4 + 1] += a * b.y;
                acc[j4 * 4 + 2] += a * b.z;
                acc[j4 * 4 + 3] += a * b.w;
            }
        }
        __syncthreads();
    }

    if (row < NN) {
#pragma unroll
        for (int j4 = 0; j4 < NC / 4; j4++) {
            float4 o;
            o.x = acc[j4 * 4 + 0] + b2[j4 * 4 + 0];
            o.y = acc[j4 * 4 + 1] + b2[j4 * 4 + 1];
            o.z = acc[j4 * 4 + 2] + b2[j4 * 4 + 2];
            o.w = acc[j4 * 4 + 3] + b2[j4 * 4 + 3];
            *(float4*)&out[row * NC + j4 * 4] = o;
        }
    }
}

// ---------------- launch ----------------
extern "C" void kernel_launch(void* const* d_in, const int* in_sizes, int n_in,
                              void* d_out, int out_size) {
    const float* x   = (const float*)d_in[0];
    const void*  ei  = d_in[1];                 // int32 or int64, detected on device
    const float* W1  = (const float*)d_in[2];
    const float* b1  = (const float*)d_in[3];
    const float* W2  = (const float*)d_in[4];
    const float* b2  = (const float*)d_in[5];
    float*       out = (float*)d_out;

    int nb1 = (NN + 511) / 512;  // 196 scan blocks

    k_detect<<<1, 256>>>(ei);
    k_zero<<<(NN + 255) / 256, 256>>>();
    k_hist<<<(NE + 255) / 256, 256>>>(ei);
    k_dinv<<<(NN + 255) / 256, 256>>>();
    k_scan1<<<nb1, 512>>>();
    k_scan2<<<1, 256>>>(nb1);
    k_scan3<<<(NN + 255) / 256, 256>>>();
    k_scatter<<<(NE + 255) / 256, 256>>>(ei);
    k_init<<<(NN * (NF / 4) + 255) / 256, 256>>>(x);

    for (int it = 0; it < NITER; it++)
        k_spmm<<<NN / 8, 256>>>(it & 1);

    k_gemm1<<<dim3(NN / 32, NH / 128), 256>>>(W1, b1);
    k_gemm2<<<(NN + 255) / 256, 256>>>(W2, b2, out);
}

// round 5
// speedup vs baseline: 1.0825x; 1.0825x over previous
#include <cuda_runtime.h>

#define NN 100000
#define NE 1200000
#define NF 64
#define NH 256
#define NC 40
#define NITER 8

// ---------------- scratch (device globals; no allocation) ----------------
__device__ int   g_is64;            // 1 if edge_index is int64, 0 if int32
__device__ int   g_cnt[NN];
__device__ float g_dinv[NN];
__device__ int   g_rowptr[NN + 1];
__device__ int   g_cursor[NN];
__device__ int   g_bsum[256];
__device__ int   g_boff[256];
__device__ __align__(16) int2  g_csr[NE];                 // {col, w as bits}
__device__ __align__(16) float g_h[(NITER + 1) * (size_t)NN * NF];  // h0..h8, 230MB

// ---------------- zero + edge dtype detection (fused) ----------------
// int64 node ids are all < NN; int32 pairs read as int64 are >= 2^32 unless
// the odd word is 0 (prob ~1e-5/sample; 1024 samples => certain detection).
__global__ void k_zero_detect(const void* ei) {
    int i = blockIdx.x * blockDim.x + threadIdx.x;
    if (i < NN) g_cnt[i] = 0;
    if (blockIdx.x == 0) {
        __shared__ int bad;
        if (threadIdx.x == 0) bad = 0;
        __syncthreads();
        const long long* e64 = (const long long*)ei;
        for (int s = threadIdx.x; s < 1024; s += blockDim.x) {
            long long v = e64[s];
            if (v < 0 || v >= NN) bad = 1;
        }
        __syncthreads();
        if (threadIdx.x == 0) g_is64 = bad ? 0 : 1;
    }
}

__device__ __forceinline__ int edge_at(const void* ei, int half, int e) {
    if (g_is64) return (int)((const long long*)ei)[(size_t)half * NE + e];
    return ((const int*)ei)[(size_t)half * NE + e];
}

__global__ void k_hist(const void* __restrict__ ei) {
    int e = blockIdx.x * blockDim.x + threadIdx.x;
    if (e < NE) atomicAdd(&g_cnt[edge_at(ei, 0, e)], 1);
}

// block-level exclusive scan (512 elems/block) + dinv fused
__global__ void k_scan1() {
    __shared__ int s[512];
    int t = threadIdx.x;
    int i = blockIdx.x * 512 + t;
    int v = (i < NN) ? g_cnt[i] : 0;
    if (i < NN) g_dinv[i] = rsqrtf((float)(v + 1));
    s[t] = v;
    __syncthreads();
    for (int off = 1; off < 512; off <<= 1) {
        int add = (t >= off) ? s[t - off] : 0;
        __syncthreads();
        s[t] += add;
        __syncthreads();
    }
    if (i < NN) g_rowptr[i] = s[t] - v;
    if (t == 511) g_bsum[blockIdx.x] = s[511];
}

__global__ void k_scan2(int nb) {
    __shared__ int s[256];
    int t = threadIdx.x;
    int v = (t < nb) ? g_bsum[t] : 0;
    s[t] = v;
    __syncthreads();
    for (int off = 1; off < 256; off <<= 1) {
        int add = (t >= off) ? s[t - off] : 0;
        __syncthreads();
        s[t] += add;
        __syncthreads();
    }
    if (t < nb) g_boff[t] = s[t] - v;
}

__global__ void k_scan3() {
    int i = blockIdx.x * blockDim.x + threadIdx.x;
    if (i < NN) {
        int rp = g_rowptr[i] + g_boff[i >> 9];
        g_rowptr[i] = rp;
        g_cursor[i] = rp;
    }
    if (i == 0) g_rowptr[NN] = NE;
}

__global__ void k_scatter(const void* __restrict__ ei) {
    int e = blockIdx.x * blockDim.x + threadIdx.x;
    if (e < NE) {
        int r = edge_at(ei, 0, e);
        int c = edge_at(ei, 1, e);
        int pos = atomicAdd(&g_cursor[r], 1);
        g_csr[pos] = make_int2(c, __float_as_int(g_dinv[r] * g_dinv[c]));
    }
}

// h0 = 0.5*x
__global__ void k_init(const float* __restrict__ x) {
    int i = blockIdx.x * blockDim.x + threadIdx.x;
    if (i < NN * (NF / 4)) {
        float4 v = ((const float4*)x)[i];
        v.x *= 0.5f; v.y *= 0.5f; v.z *= 0.5f; v.w *= 0.5f;
        ((float4*)g_h)[i] = v;
    }
}

// ---------------- SPMM: h_{it+1} = A_norm h_it ----------------
// one warp per row, lane = 2 features (float2); pure write, no y RMW
__global__ void __launch_bounds__(256) k_spmm(int it) {
    const size_t NNF = (size_t)NN * NF;
    const float2* __restrict__ hin = (const float2*)(g_h + (size_t)it * NNF);
    float2* __restrict__ hout      = (float2*)(g_h + (size_t)(it + 1) * NNF);

    __shared__ int2 se[8][32];

    int lane = threadIdx.x & 31;
    int wid  = threadIdx.x >> 5;
    int r    = blockIdx.x * 8 + wid;   // NN divisible by 8

    int start = g_rowptr[r];
    int end   = g_rowptr[r + 1];
    float dr  = g_dinv[r];

    float2 hv = __ldg(&hin[r * 32 + lane]);
    float dw  = dr * dr;
    float2 acc;
    acc.x = dw * hv.x;
    acc.y = dw * hv.y;

    for (int b = start; b < end; b += 32) {
        int idx = b + lane;
        int2 e = make_int2(0, 0);      // w=0 => harmless dummy gather of row 0
        if (idx < end) e = g_csr[idx];
        se[wid][lane] = e;
        __syncwarp();
        int m = min(32, end - b);
#pragma unroll 4
        for (int j = 0; j < m; j++) {
            int2  ej = se[wid][j];
            float wj = __int_as_float(ej.y);
            float2 t = __ldg(&hin[ej.x * 32 + lane]);
            acc.x += wj * t.x;
            acc.y += wj * t.y;
        }
        __syncwarp();
    }

    hout[r * 32 + lane] = acc;
}

// ---------------- fused MLP: out = relu((avg(h)) @ W1 + b1) @ W2 + b2 ------
// block = 32 rows; hid processed in 4 chunks of 64 cols, never materialized.
__global__ void __launch_bounds__(256) k_mlp(const float* __restrict__ W1,
                                             const float* __restrict__ b1,
                                             const float* __restrict__ W2,
                                             const float* __restrict__ b2,
                                             float* __restrict__ out) {
    __shared__ __align__(16) float As[32 * 68];    // 8.7 KB  (padded stride 68)
    __shared__ __align__(16) float W1c[64 * 64];   // 16 KB
    __shared__ __align__(16) float Hs[32 * 68];    // 8.7 KB
    __shared__ __align__(16) float W2cT[40 * 68];  // 10.9 KB (transposed, padded)
    __shared__ float sb1[64];

    int tid = threadIdx.x;
    int rb  = blockIdx.x * 32;        // NN divisible by 32

    // As = (1/9) * sum_{b=0..8} h_b  [32 x 64]
    const float inv = 1.0f / (NITER + 1);
    const size_t NNF = (size_t)NN * NF;
    for (int l = tid; l < 32 * 16; l += 256) {
        int rr = l >> 4, k4 = l & 15;
        float4 s = make_float4(0.f, 0.f, 0.f, 0.f);
#pragma unroll
        for (int b = 0; b <= NITER; b++) {
            const float4* hb = (const float4*)(g_h + (size_t)b * NNF);
            float4 v = __ldg(&hb[(size_t)(rb + rr) * 16 + k4]);
            s.x += v.x; s.y += v.y; s.z += v.z; s.w += v.w;
        }
        s.x *= inv; s.y *= inv; s.z *= inv; s.w *= inv;
        *(float4*)&As[rr * 68 + k4 * 4] = s;
    }

    int tx  = tid & 15, ty = tid >> 4;   // hid-compute mapping: 2 rows x 4 cols
    int row = tid >> 3, cg = tid & 7;    // gemm2 mapping: 1 row x 5 cols
    float acc5[5] = {0.f, 0.f, 0.f, 0.f, 0.f};

    for (int c = 0; c < 4; c++) {
        __syncthreads();   // Hs of prev chunk fully consumed; safe to reload
        // W1 chunk [64 x 64]
        for (int l = tid; l < 64 * 16; l += 256) {
            int kk = l >> 4, j4 = l & 15;
            *(float4*)&W1c[kk * 64 + j4 * 4] =
                __ldg((const float4*)&W1[kk * NH + c * 64 + j4 * 4]);
        }
        // W2 chunk transposed: W2[(c*64+k)*40 + cc] -> W2cT[cc*68 + k]
        for (int l = tid; l < 64 * 40; l += 256) {
            int kk = l / 40, cc = l - kk * 40;
            W2cT[cc * 68 + kk] = __ldg(&W2[(c * 64 + kk) * NC + cc]);
        }
        if (tid < 64) sb1[tid] = __ldg(&b1[c * 64 + tid]);
        __syncthreads();

        // hid tile in regs: rows ty*2+{0,1}, cols tx*4..tx*4+3, K=64
        float4 hh0 = make_float4(0.f, 0.f, 0.f, 0.f);
        float4 hh1 = make_float4(0.f, 0.f, 0.f, 0.f);
#pragma unroll
        for (int k = 0; k < 64; k++) {
            float4 w = *(const float4*)&W1c[k * 64 + tx * 4];
            float a0 = As[(ty * 2 + 0) * 68 + k];
            float a1 = As[(ty * 2 + 1) * 68 + k];
            hh0.x += a0 * w.x; hh0.y += a0 * w.y; hh0.z += a0 * w.z; hh0.w += a0 * w.w;
            hh1.x += a1 * w.x; hh1.y += a1 * w.y; hh1.z += a1 * w.z; hh1.w += a1 * w.w;
        }
        float bx = sb1[tx * 4], by = sb1[tx * 4 + 1],
              bz = sb1[tx * 4 + 2], bw = sb1[tx * 4 + 3];
        float4 o0, o1;
        o0.x = fmaxf(hh0.x + bx, 0.f); o0.y = fmaxf(hh0.y + by, 0.f);
        o0.z = fmaxf(hh0.z + bz, 0.f); o0.w = fmaxf(hh0.w + bw, 0.f);
        o1.x = fmaxf(hh1.x + bx, 0.f); o1.y = fmaxf(hh1.y + by, 0.f);
        o1.z = fmaxf(hh1.z + bz, 0.f); o1.w = fmaxf(hh1.w + bw, 0.f);
        *(float4*)&Hs[(ty * 2 + 0) * 68 + tx * 4] = o0;
        *(float4*)&Hs[(ty * 2 + 1) * 68 + tx * 4] = o1;
        __syncthreads();

        // gemm2 partial: acc5 += Hs[row, :64] . W2cT[col, :64]
#pragma unroll
        for (int k4 = 0; k4 < 16; k4++) {
            float4 h = *(const float4*)&Hs[row * 68 + k4 * 4];
#pragma unroll
            for (int j = 0; j < 5; j++) {
                float4 w = *(const float4*)&W2cT[(cg * 5 + j) * 68 + k4 * 4];
                acc5[j] += h.x * w.x + h.y * w.y + h.z * w.z + h.w * w.w;
            }
        }
    }

#pragma unroll
    for (int j = 0; j < 5; j++)
        out[(size_t)(rb + row) * NC + cg * 5 + j] = acc5[j] + __ldg(&b2[cg * 5 + j]);
}

// ---------------- launch ----------------
extern "C" void kernel_launch(void* const* d_in, const int* in_sizes, int n_in,
                              void* d_out, int out_size) {
    const float* x   = (const float*)d_in[0];
    const void*  ei  = d_in[1];                 // int32 or int64, detected on device
    const float* W1  = (const float*)d_in[2];
    const float* b1  = (const float*)d_in[3];
    const float* W2  = (const float*)d_in[4];
    const float* b2  = (const float*)d_in[5];
    float*       out = (float*)d_out;

    int nb1 = (NN + 511) / 512;  // 196 scan blocks

    k_zero_detect<<<(NN + 255) / 256, 256>>>(ei);
    k_hist<<<(NE + 255) / 256, 256>>>(ei);
    k_scan1<<<nb1, 512>>>();
    k_scan2<<<1, 256>>>(nb1);
    k_scan3<<<(NN + 255) / 256, 256>>>();
    k_scatter<<<(NE + 255) / 256, 256>>>(ei);
    k_init<<<(NN * (NF / 4) + 255) / 256, 256>>>(x);

    for (int it = 0; it < NITER; it++)
        k_spmm<<<NN / 8, 256>>>(it);

    k_mlp<<<NN / 32, 256>>>(W1, b1, W2, b2, out);
}

// round 6
// speedup vs baseline: 1.1296x; 1.0435x over previous
#include <cuda_runtime.h>
#include <cuda_fp16.h>

#define NN 100000
#define NE 1200000
#define NF 64
#define NH 256
#define NC 40
#define NITER 8

// ---------------- scratch (device globals; no allocation) ----------------
__device__ int   g_is64;            // 1 if edge_index is int64, 0 if int32
__device__ int   g_cnt[NN];
__device__ float g_dinv[NN];
__device__ int   g_rowptr[NN + 1];
__device__ int   g_cursor[NN];
__device__ int   g_bsum[256];
__device__ int   g_boff[256];
__device__ __align__(16) int2    g_csr[NE];                      // {col, w bits}
// h0..h8 in fp16: (9 * 100000 * 32) half2 = 115 MB. Row = 32 half2 = 128 B.
__device__ __align__(16) __half2 g_hh[(NITER + 1) * (size_t)NN * (NF / 2)];

// ---------------- zero + edge dtype detection (fused) ----------------
// int64 node ids are all < NN; int32 pairs read as int64 are >= 2^32 unless
// the odd word is 0 (prob ~1e-5/sample; 1024 samples => certain detection).
__global__ void k_zero_detect(const void* ei) {
    int i = blockIdx.x * blockDim.x + threadIdx.x;
    if (i < NN) g_cnt[i] = 0;
    if (blockIdx.x == 0) {
        __shared__ int bad;
        if (threadIdx.x == 0) bad = 0;
        __syncthreads();
        const long long* e64 = (const long long*)ei;
        for (int s = threadIdx.x; s < 1024; s += blockDim.x) {
            long long v = e64[s];
            if (v < 0 || v >= NN) bad = 1;
        }
        __syncthreads();
        if (threadIdx.x == 0) g_is64 = bad ? 0 : 1;
    }
}

__device__ __forceinline__ int edge_at(const void* ei, int half, int e) {
    if (g_is64) return (int)((const long long*)ei)[(size_t)half * NE + e];
    return ((const int*)ei)[(size_t)half * NE + e];
}

__global__ void k_hist(const void* __restrict__ ei) {
    int e = blockIdx.x * blockDim.x + threadIdx.x;
    if (e < NE) atomicAdd(&g_cnt[edge_at(ei, 0, e)], 1);
}

// block-level exclusive scan (512 elems/block) + dinv fused
__global__ void k_scan1() {
    __shared__ int s[512];
    int t = threadIdx.x;
    int i = blockIdx.x * 512 + t;
    int v = (i < NN) ? g_cnt[i] : 0;
    if (i < NN) g_dinv[i] = rsqrtf((float)(v + 1));
    s[t] = v;
    __syncthreads();
    for (int off = 1; off < 512; off <<= 1) {
        int add = (t >= off) ? s[t - off] : 0;
        __syncthreads();
        s[t] += add;
        __syncthreads();
    }
    if (i < NN) g_rowptr[i] = s[t] - v;
    if (t == 511) g_bsum[blockIdx.x] = s[511];
}

__global__ void k_scan2(int nb) {
    __shared__ int s[256];
    int t = threadIdx.x;
    int v = (t < nb) ? g_bsum[t] : 0;
    s[t] = v;
    __syncthreads();
    for (int off = 1; off < 256; off <<= 1) {
        int add = (t >= off) ? s[t - off] : 0;
        __syncthreads();
        s[t] += add;
        __syncthreads();
    }
    if (t < nb) g_boff[t] = s[t] - v;
}

__global__ void k_scan3() {
    int i = blockIdx.x * blockDim.x + threadIdx.x;
    if (i < NN) {
        int rp = g_rowptr[i] + g_boff[i >> 9];
        g_rowptr[i] = rp;
        g_cursor[i] = rp;
    }
    if (i == 0) g_rowptr[NN] = NE;
}

__global__ void k_scatter(const void* __restrict__ ei) {
    int e = blockIdx.x * blockDim.x + threadIdx.x;
    if (e < NE) {
        int r = edge_at(ei, 0, e);
        int c = edge_at(ei, 1, e);
        int pos = atomicAdd(&g_cursor[r], 1);
        g_csr[pos] = make_int2(c, __float_as_int(g_dinv[r] * g_dinv[c]));
    }
}

// h0 = 0.5*x  (fp32 -> fp16 storage)
__global__ void k_init(const float* __restrict__ x) {
    int i = blockIdx.x * blockDim.x + threadIdx.x;   // each handles 4 floats
    if (i < NN * (NF / 4)) {
        float4 v = ((const float4*)x)[i];
        __half2 a = __floats2half2_rn(v.x * 0.5f, v.y * 0.5f);
        __half2 b = __floats2half2_rn(v.z * 0.5f, v.w * 0.5f);
        *(uint2*)&g_hh[(size_t)i * 2] =
            make_uint2(*(unsigned*)&a, *(unsigned*)&b);
    }
}

// ---------------- SPMM: h_{it+1} = A_norm h_it (fp16 storage, fp32 math) ----
// one warp per row, lane = 2 features (half2 = 4B; warp gather = 128B line)
__global__ void __launch_bounds__(256) k_spmm(int it) {
    const size_t NN32 = (size_t)NN * (NF / 2);
    const __half2* __restrict__ hin = g_hh + (size_t)it * NN32;
    __half2* __restrict__ hout      = g_hh + (size_t)(it + 1) * NN32;

    __shared__ int2 se[8][32];

    int lane = threadIdx.x & 31;
    int wid  = threadIdx.x >> 5;
    int r    = blockIdx.x * 8 + wid;   // NN divisible by 8

    int start = g_rowptr[r];
    int end   = g_rowptr[r + 1];
    float dr  = g_dinv[r];

    float2 hv = __half22float2(__ldg(&hin[(size_t)r * 32 + lane]));
    float dw  = dr * dr;
    float2 acc;
    acc.x = dw * hv.x;
    acc.y = dw * hv.y;

    for (int b = start; b < end; b += 32) {
        int idx = b + lane;
        int2 e = make_int2(0, 0);      // w=0 => harmless dummy gather of row 0
        if (idx < end) e = g_csr[idx];
        se[wid][lane] = e;
        __syncwarp();
        int m = min(32, end - b);
#pragma unroll 4
        for (int j = 0; j < m; j++) {
            int2  ej = se[wid][j];
            float wj = __int_as_float(ej.y);
            float2 t = __half22float2(__ldg(&hin[(size_t)ej.x * 32 + lane]));
            acc.x += wj * t.x;
            acc.y += wj * t.y;
        }
        __syncwarp();
    }

    hout[(size_t)r * 32 + lane] = __floats2half2_rn(acc.x, acc.y);
}

// ---------------- fused MLP: out = relu((avg(h)) @ W1 + b1) @ W2 + b2 ------
// block = 32 rows; hid processed in 4 chunks of 64 cols, never materialized.
__global__ void __launch_bounds__(256) k_mlp(const float* __restrict__ W1,
                                             const float* __restrict__ b1,
                                             const float* __restrict__ W2,
                                             const float* __restrict__ b2,
                                             float* __restrict__ out) {
    __shared__ __align__(16) float As[32 * 68];    // 8.7 KB  (padded stride 68)
    __shared__ __align__(16) float W1c[64 * 64];   // 16 KB
    __shared__ __align__(16) float Hs[32 * 68];    // 8.7 KB
    __shared__ __align__(16) float W2cT[40 * 68];  // 10.9 KB (transposed, padded)
    __shared__ float sb1[64];

    int tid = threadIdx.x;
    int rb  = blockIdx.x * 32;        // NN divisible by 32

    // As = (1/9) * sum_{b=0..8} h_b  [32 x 64], fp32 accumulation
    const float inv = 1.0f / (NITER + 1);
    const size_t NN32 = (size_t)NN * (NF / 2);
    for (int l = tid; l < 32 * 16; l += 256) {   // 512 quads of 4 feats
        int rr = l >> 4, q = l & 15;             // q indexes 2 half2 = 4 feats
        float4 s = make_float4(0.f, 0.f, 0.f, 0.f);
#pragma unroll
        for (int b = 0; b <= NITER; b++) {
            const uint2* hb = (const uint2*)(g_hh + (size_t)b * NN32);
            uint2 v = __ldg(&hb[(size_t)(rb + rr) * 16 + q]);
            float2 f0 = __half22float2(*(__half2*)&v.x);
            float2 f1 = __half22float2(*(__half2*)&v.y);
            s.x += f0.x; s.y += f0.y; s.z += f1.x; s.w += f1.y;
        }
        s.x *= inv; s.y *= inv; s.z *= inv; s.w *= inv;
        *(float4*)&As[rr * 68 + q * 4] = s;
    }

    int tx  = tid & 15, ty = tid >> 4;   // hid-compute mapping: 2 rows x 4 cols
    int row = tid >> 3, cg = tid & 7;    // gemm2 mapping: 1 row x 5 cols
    float acc5[5] = {0.f, 0.f, 0.f, 0.f, 0.f};

    for (int c = 0; c < 4; c++) {
        __syncthreads();   // Hs of prev chunk fully consumed; safe to reload
        // W1 chunk [64 x 64]
        for (int l = tid; l < 64 * 16; l += 256) {
            int kk = l >> 4, j4 = l & 15;
            *(float4*)&W1c[kk * 64 + j4 * 4] =
                __ldg((const float4*)&W1[kk * NH + c * 64 + j4 * 4]);
        }
        // W2 chunk transposed: W2[(c*64+k)*40 + cc] -> W2cT[cc*68 + k]
        for (int l = tid; l < 64 * 40; l += 256) {
            int kk = l / 40, cc = l - kk * 40;
            W2cT[cc * 68 + kk] = __ldg(&W2[(c * 64 + kk) * NC + cc]);
        }
        if (tid < 64) sb1[tid] = __ldg(&b1[c * 64 + tid]);
        __syncthreads();

        // hid tile in regs: rows ty*2+{0,1}, cols tx*4..tx*4+3, K=64
        float4 hh0 = make_float4(0.f, 0.f, 0.f, 0.f);
        float4 hh1 = make_float4(0.f, 0.f, 0.f, 0.f);
#pragma unroll
        for (int k = 0; k < 64; k++) {
            float4 w = *(const float4*)&W1c[k * 64 + tx * 4];
            float a0 = As[(ty * 2 + 0) * 68 + k];
            float a1 = As[(ty * 2 + 1) * 68 + k];
            hh0.x += a0 * w.x; hh0.y += a0 * w.y; hh0.z += a0 * w.z; hh0.w += a0 * w.w;
            hh1.x += a1 * w.x; hh1.y += a1 * w.y; hh1.z += a1 * w.z; hh1.w += a1 * w.w;
        }
        float bx = sb1[tx * 4], by = sb1[tx * 4 + 1],
              bz = sb1[tx * 4 + 2], bw = sb1[tx * 4 + 3];
        float4 o0, o1;
        o0.x = fmaxf(hh0.x + bx, 0.f); o0.y = fmaxf(hh0.y + by, 0.f);
        o0.z = fmaxf(hh0.z + bz, 0.f); o0.w = fmaxf(hh0.w + bw, 0.f);
        o1.x = fmaxf(hh1.x + bx, 0.f); o1.y = fmaxf(hh1.y + by, 0.f);
        o1.z = fmaxf(hh1.z + bz, 0.f); o1.w = fmaxf(hh1.w + bw, 0.f);
        *(float4*)&Hs[(ty * 2 + 0) * 68 + tx * 4] = o0;
        *(float4*)&Hs[(ty * 2 + 1) * 68 + tx * 4] = o1;
        __syncthreads();

        // gemm2 partial: acc5 += Hs[row, :64] . W2cT[col, :64]
#pragma unroll
        for (int k4 = 0; k4 < 16; k4++) {
            float4 h = *(const float4*)&Hs[row * 68 + k4 * 4];
#pragma unroll
            for (int j = 0; j < 5; j++) {
                float4 w = *(const float4*)&W2cT[(cg * 5 + j) * 68 + k4 * 4];
                acc5[j] += h.x * w.x + h.y * w.y + h.z * w.z + h.w * w.w;
            }
        }
    }

#pragma unroll
    for (int j = 0; j < 5; j++)
        out[(size_t)(rb + row) * NC + cg * 5 + j] = acc5[j] + __ldg(&b2[cg * 5 + j]);
}

// ---------------- launch ----------------
extern "C" void kernel_launch(void* const* d_in, const int* in_sizes, int n_in,
                              void* d_out, int out_size) {
    const float* x   = (const float*)d_in[0];
    const void*  ei  = d_in[1];                 // int32 or int64, detected on device
    const float* W1  = (const float*)d_in[2];
    const float* b1  = (const float*)d_in[3];
    const float* W2  = (const float*)d_in[4];
    const float* b2  = (const float*)d_in[5];
    float*       out = (float*)d_out;

    int nb1 = (NN + 511) / 512;  // 196 scan blocks

    k_zero_detect<<<(NN + 255) / 256, 256>>>(ei);
    k_hist<<<(NE + 255) / 256, 256>>>(ei);
    k_scan1<<<nb1, 512>>>();
    k_scan2<<<1, 256>>>(nb1);
    k_scan3<<<(NN + 255) / 256, 256>>>();
    k_scatter<<<(NE + 255) / 256, 256>>>(ei);
    k_init<<<(NN * (NF / 4) + 255) / 256, 256>>>(x);

    for (int it = 0; it < NITER; it++)
        k_spmm<<<NN / 8, 256>>>(it);

    k_mlp<<<NN / 32, 256>>>(W1, b1, W2, b2, out);
}